// round 9
// baseline (speedup 1.0000x reference)
#include <cuda_runtime.h>

#define BB 4
#define LL 5
#define CC 256
#define HH 100
#define WW 252
#define HWTOT (HH*WW)        // 25200
#define BL (BB*LL)           // 20
#define CP 2
#define KSEL 1024
#define HW4 (HWTOT/4)        // 6300
#define CHW4 (CC*HWTOT/4)    // 1,612,800 float4 per (b,l)
#define NPT 25               // values per thread in prep (1024*25 >= 25200)
#define CPB 8                // channels per apply block

__device__ unsigned char g_factor[BL*HWTOT];   // ~0.5 MB (only kept slices used)

// ---------------------------------------------------------------------------
// Prep: one block per (b,l); only "kept" slices (l>0 && mask!=0) do work.
// fmap = sigmoid(max_cp(psm - ego)) held in registers; exact K-th largest via
// MSB-first 8-bit radix select on the float bits (positive -> order-isomorphic).
// Histogram atomics are warp-aggregated (match_any) because sigmoid outputs
// cluster into 2-3 exponent bins, which serialized plain smem atomics.
// Tie semantics (>= exact K-th value) identical to reference.
// ---------------------------------------------------------------------------
__global__ __launch_bounds__(1024) void prep_kernel(const float* __restrict__ psm,
                                                    const int* __restrict__ mask) {
    int bl = blockIdx.x;
    int l  = bl % LL;
    int b  = bl / LL;
    if (l == 0 || mask[bl] == 0) return;   // apply_kernel handles these directly

    int tid  = threadIdx.x;
    int lane = tid & 31;
    unsigned char* fac = g_factor + bl * HWTOT;

    const float* p = psm + (size_t)bl * CP * HWTOT;          // psm[b,l,0,:]
    const float* e = psm + (size_t)b * LL * CP * HWTOT;      // psm[b,0,0,:]

    unsigned vals[NPT];
    #pragma unroll
    for (int k = 0; k < NPT; k++) {
        int i = tid + k * 1024;
        unsigned u = 0;
        if (k < 24 || i < HWTOT) {
            float d0 = __ldg(p + i)         - __ldg(e + i);
            float d1 = __ldg(p + i + HWTOT) - __ldg(e + i + HWTOT);
            float d  = fmaxf(d0, d1);
            u = __float_as_uint(1.0f / (1.0f + expf(-d)));
        }
        vals[k] = u;
    }

    __shared__ unsigned hist[256];
    __shared__ unsigned s_prefix, s_k;
    if (tid == 0) { s_prefix = 0u; s_k = KSEL; }

    for (int shift = 24; shift >= 0; shift -= 8) {
        for (int i = tid; i < 256; i += 1024) hist[i] = 0;
        __syncthreads();
        unsigned pre     = s_prefix;
        unsigned premask = (shift == 24) ? 0u : (0xFFFFFFFFu << (shift + 8));
        #pragma unroll
        for (int k = 0; k < NPT; k++) {
            int i = tid + k * 1024;
            bool participate = (k < 24 || i < HWTOT) && ((vals[k] & premask) == pre);
            unsigned m = __ballot_sync(0xFFFFFFFFu, participate);
            if (participate) {
                unsigned bin  = (vals[k] >> shift) & 0xFFu;
                unsigned same = __match_any_sync(m, bin);
                if (lane == (__ffs(same) - 1))
                    atomicAdd(&hist[bin], (unsigned)__popc(same));
            }
        }
        __syncthreads();
        if (tid == 0) {
            unsigned k = s_k, cum = 0;
            int bin = 255;
            for (; bin > 0; bin--) {
                if (cum + hist[bin] >= k) break;
                cum += hist[bin];
            }
            s_prefix = pre | ((unsigned)bin << shift);
            s_k      = k - cum;
        }
        __syncthreads();
    }

    unsigned thr = s_prefix;
    #pragma unroll
    for (int k = 0; k < NPT; k++) {
        int i = tid + k * 1024;
        if (k < 24 || i < HWTOT)
            fac[i] = (vals[k] >= thr) ? 1 : 0;
    }
}

// ---------------------------------------------------------------------------
// Apply: block = 256 contiguous hw4 positions x CPB=8 channels.
// One factor load gates 8 channel elements (factor is C-invariant).
// l==0 -> straight copy (no factor); mask==0 -> zeros (no loads at all);
// kept  -> factor-gated, skipping x reads for fully-zero float4s.
// MLP=8 on the x-load chain; streaming stores (write-once output).
// ---------------------------------------------------------------------------
__global__ __launch_bounds__(256) void apply_kernel(const float4* __restrict__ x,
                                                    float4* __restrict__ out,
                                                    const int* __restrict__ mask) {
    int bl  = blockIdx.z;
    int l   = bl % LL;
    int hw4 = blockIdx.x * 256 + threadIdx.x;
    if (hw4 >= HW4) return;
    int c0 = blockIdx.y * CPB;
    size_t base = (size_t)bl * CHW4 + (size_t)c0 * HW4 + hw4;

    const float4 zero = make_float4(0.f, 0.f, 0.f, 0.f);

    if (l != 0 && mask[bl] == 0) {
        #pragma unroll
        for (int j = 0; j < CPB; j++) __stcs(out + base + j * HW4, zero);
        return;
    }
    if (l == 0) {
        float4 v[CPB];
        #pragma unroll
        for (int j = 0; j < CPB; j++) v[j] = __ldg(x + base + j * HW4);
        #pragma unroll
        for (int j = 0; j < CPB; j++) __stcs(out + base + j * HW4, v[j]);
        return;
    }

    uchar4 f = __ldg(reinterpret_cast<const uchar4*>(g_factor + bl * HWTOT + hw4 * 4));
    if ((f.x | f.y | f.z | f.w) == 0) {
        #pragma unroll
        for (int j = 0; j < CPB; j++) __stcs(out + base + j * HW4, zero);
    } else {
        float fx = (float)f.x, fy = (float)f.y, fz = (float)f.z, fw = (float)f.w;
        float4 v[CPB];
        #pragma unroll
        for (int j = 0; j < CPB; j++) v[j] = __ldg(x + base + j * HW4);
        #pragma unroll
        for (int j = 0; j < CPB; j++) {
            v[j].x *= fx; v[j].y *= fy; v[j].z *= fz; v[j].w *= fw;
            __stcs(out + base + j * HW4, v[j]);
        }
    }
}

// ---------------------------------------------------------------------------
extern "C" void kernel_launch(void* const* d_in, const int* in_sizes, int n_in,
                              void* d_out, int out_size) {
    const float* x    = (const float*)d_in[0];
    const float* psm  = (const float*)d_in[1];
    const int*   mask = (const int*)d_in[2];

    prep_kernel<<<BL, 1024>>>(psm, mask);

    dim3 grid((HW4 + 255) / 256, CC / CPB, BL);   // 25 x 32 x 20 blocks
    apply_kernel<<<grid, 256>>>((const float4*)x, (float4*)d_out, mask);
}

// round 10
// speedup vs baseline: 1.1343x; 1.1343x over previous
#include <cuda_runtime.h>

#define BB 4
#define LL 5
#define CC 256
#define HH 100
#define WW 252
#define HWTOT (HH*WW)        // 25200
#define BL (BB*LL)           // 20
#define CP 2
#define KSEL 1024
#define HW4 (HWTOT/4)        // 6300
#define CHW4 (CC*HWTOT/4)    // 1,612,800 float4 per (b,l)
#define NPT 25               // values per thread in prep (1024*25 >= 25200)

__device__ unsigned char g_factor[BL*HWTOT];   // ~0.5 MB

// ---------------------------------------------------------------------------
// Prep: one block per (b,l).
//  l==0         -> factor = 1 (vectorized fill)
//  mask==0, l>0 -> factor = 0 (vectorized fill)
//  kept         -> fmap = sigmoid(max_cp(psm - ego)) in REGISTERS, exact K-th
//                  largest via MSB-first 8-bit radix select on float bits
//                  (positive -> order-isomorphic). Histogram atomics are
//                  warp-aggregated (match_any): sigmoid outputs cluster into
//                  2-3 exponent bins, which serializes plain smem atomics at
//                  32 cyc/warp. Tie semantics (>= exact K-th) == reference.
// ---------------------------------------------------------------------------
__global__ __launch_bounds__(1024) void prep_kernel(const float* __restrict__ psm,
                                                    const int* __restrict__ mask) {
    int bl = blockIdx.x;
    int l  = bl % LL;
    int b  = bl / LL;
    int tid  = threadIdx.x;
    int lane = tid & 31;
    unsigned char* fac = g_factor + bl * HWTOT;

    if (l == 0 || mask[bl] == 0) {
        // HWTOT = 25200 = 1575 * 16 -> exact int4 fill
        int fillv = (l == 0) ? 0x01010101 : 0;
        int4 q = make_int4(fillv, fillv, fillv, fillv);
        int4* dst = reinterpret_cast<int4*>(fac);
        for (int i = tid; i < HWTOT / 16; i += 1024) dst[i] = q;
        return;
    }

    const float* p = psm + (size_t)bl * CP * HWTOT;          // psm[b,l,0,:]
    const float* e = psm + (size_t)b * LL * CP * HWTOT;      // psm[b,0,0,:]

    unsigned vals[NPT];
    #pragma unroll
    for (int k = 0; k < NPT; k++) {
        int i = tid + k * 1024;
        unsigned u = 0;
        if (k < 24 || i < HWTOT) {
            float d0 = __ldg(p + i)         - __ldg(e + i);
            float d1 = __ldg(p + i + HWTOT) - __ldg(e + i + HWTOT);
            float d  = fmaxf(d0, d1);
            u = __float_as_uint(1.0f / (1.0f + expf(-d)));
        }
        vals[k] = u;
    }

    __shared__ unsigned hist[256];
    __shared__ unsigned s_prefix, s_k;
    if (tid == 0) { s_prefix = 0u; s_k = KSEL; }

    for (int shift = 24; shift >= 0; shift -= 8) {
        for (int i = tid; i < 256; i += 1024) hist[i] = 0;
        __syncthreads();
        unsigned pre     = s_prefix;
        unsigned premask = (shift == 24) ? 0u : (0xFFFFFFFFu << (shift + 8));
        #pragma unroll
        for (int k = 0; k < NPT; k++) {
            int i = tid + k * 1024;
            bool participate = (k < 24 || i < HWTOT) && ((vals[k] & premask) == pre);
            unsigned m = __ballot_sync(0xFFFFFFFFu, participate);
            if (participate) {
                unsigned bin  = (vals[k] >> shift) & 0xFFu;
                unsigned same = __match_any_sync(m, bin);
                if (lane == (__ffs(same) - 1))
                    atomicAdd(&hist[bin], (unsigned)__popc(same));
            }
        }
        __syncthreads();
        if (tid == 0) {
            unsigned k = s_k, cum = 0;
            int bin = 255;
            for (; bin > 0; bin--) {
                if (cum + hist[bin] >= k) break;
                cum += hist[bin];
            }
            s_prefix = pre | ((unsigned)bin << shift);
            s_k      = k - cum;
        }
        __syncthreads();
    }

    unsigned thr = s_prefix;
    #pragma unroll
    for (int k = 0; k < NPT; k++) {
        int i = tid + k * 1024;
        if (k < 24 || i < HWTOT)
            fac[i] = (vals[k] >= thr) ? 1 : 0;
    }
}

// ---------------------------------------------------------------------------
// Heavy streaming pass (R7 layout — best measured: 109us @ 82.4% DRAM).
// 4 contiguous-strided float4 per thread; block covers one contiguous 16KB
// region (DRAM row locality). Factor loaded first; x read skipped when the
// whole float4 is gated. Streaming stores (write-once output).
// ---------------------------------------------------------------------------
__global__ __launch_bounds__(256) void apply_kernel(const float4* __restrict__ x,
                                                    float4* __restrict__ out) {
    int bl   = blockIdx.y;
    int base = blockIdx.x * 1024 + threadIdx.x;   // block covers 1024 float4s
    const unsigned char* fac = g_factor + bl * HWTOT;

    int      idx[4];
    uchar4   f[4];
    #pragma unroll
    for (int j = 0; j < 4; j++) {
        idx[j] = base + j * 256;                  // < CHW4 exactly (1575*1024)
        int hw4 = idx[j] % HW4;
        f[j] = __ldg(reinterpret_cast<const uchar4*>(fac + hw4 * 4));
    }

    float4 v[4];
    #pragma unroll
    for (int j = 0; j < 4; j++) {
        if ((f[j].x | f[j].y | f[j].z | f[j].w) == 0) {
            v[j] = make_float4(0.f, 0.f, 0.f, 0.f);
        } else {
            v[j] = __ldg(x + (size_t)bl * CHW4 + idx[j]);
            v[j].x *= (float)f[j].x; v[j].y *= (float)f[j].y;
            v[j].z *= (float)f[j].z; v[j].w *= (float)f[j].w;
        }
    }

    #pragma unroll
    for (int j = 0; j < 4; j++)
        __stcs(out + (size_t)bl * CHW4 + idx[j], v[j]);
}

// ---------------------------------------------------------------------------
extern "C" void kernel_launch(void* const* d_in, const int* in_sizes, int n_in,
                              void* d_out, int out_size) {
    const float* x    = (const float*)d_in[0];
    const float* psm  = (const float*)d_in[1];
    const int*   mask = (const int*)d_in[2];

    prep_kernel<<<BL, 1024>>>(psm, mask);

    dim3 grid(CHW4 / 1024, BL);    // 1575 x 20 blocks, 4 float4/thread
    apply_kernel<<<grid, 256>>>((const float4*)x, (float4*)d_out);
}

// round 11
// speedup vs baseline: 1.3745x; 1.2118x over previous
#include <cuda_runtime.h>

#define BB 4
#define LL 5
#define CC 256
#define HH 100
#define WW 252
#define HWTOT (HH*WW)        // 25200
#define BL (BB*LL)           // 20
#define CP 2
#define KSEL 1024
#define HW4 (HWTOT/4)        // 6300
#define CHW4 (CC*HWTOT/4)    // 1,612,800 float4 per (b,l)
#define NPT 25               // values per thread in prep (1024*25 >= 25200)

__device__ unsigned char g_factor[BL*HWTOT];   // ~0.5 MB

// ---------------------------------------------------------------------------
// Prep: one block per (b,l).
//  l==0         -> factor = 1 (int4 fill)
//  mask==0, l>0 -> factor = 0 (int4 fill)
//  kept         -> fmap = sigmoid(max_cp(psm - ego)) in REGISTERS; exact K-th
//                  largest via 3-round MSB-first radix select (11/11/10 bits,
//                  2048-bin histogram). Wide bins kill the atomics
//                  serialization that 256-bin rounds suffered (sigmoid values
//                  cluster in 2-3 top-byte bins but spread fine over 11 bits).
//                  Positive floats -> bit pattern order-isomorphic; ">= exact
//                  K-th value" matches reference tie semantics.
// ---------------------------------------------------------------------------
__global__ __launch_bounds__(1024) void prep_kernel(const float* __restrict__ psm,
                                                    const int* __restrict__ mask) {
    int bl  = blockIdx.x;
    int l   = bl % LL;
    int b   = bl / LL;
    int tid = threadIdx.x;
    unsigned char* fac = g_factor + bl * HWTOT;

    if (l == 0 || mask[bl] == 0) {
        int fillv = (l == 0) ? 0x01010101 : 0;
        int4 q = make_int4(fillv, fillv, fillv, fillv);
        int4* dst = reinterpret_cast<int4*>(fac);
        for (int i = tid; i < HWTOT / 16; i += 1024) dst[i] = q;   // 25200 = 1575*16
        return;
    }

    const float* p = psm + (size_t)bl * CP * HWTOT;          // psm[b,l,0,:]
    const float* e = psm + (size_t)b * LL * CP * HWTOT;      // psm[b,0,0,:]

    unsigned vals[NPT];
    #pragma unroll
    for (int k = 0; k < NPT; k++) {
        int i = tid + k * 1024;
        unsigned u = 0;
        if (k < 24 || i < HWTOT) {
            float d0 = __ldg(p + i)         - __ldg(e + i);
            float d1 = __ldg(p + i + HWTOT) - __ldg(e + i + HWTOT);
            float d  = fmaxf(d0, d1);
            u = __float_as_uint(1.0f / (1.0f + expf(-d)));
        }
        vals[k] = u;
    }

    __shared__ unsigned hist[2048];
    __shared__ unsigned gsum[64];
    __shared__ unsigned s_prefix, s_k;
    if (tid == 0) { s_prefix = 0u; s_k = KSEL; }

    const int r_shift[3] = {21, 10, 0};
    const int r_bits[3]  = {11, 11, 10};

    for (int r = 0; r < 3; r++) {
        int shift      = r_shift[r];
        int nb         = 1 << r_bits[r];
        unsigned bmask = (unsigned)nb - 1u;

        for (int i = tid; i < nb; i += 1024) hist[i] = 0;
        __syncthreads();

        unsigned pre     = s_prefix;
        unsigned premask = (r == 0) ? 0u : (0xFFFFFFFFu << (shift + r_bits[r]));

        #pragma unroll
        for (int k = 0; k < NPT; k++) {
            int i = tid + k * 1024;
            if ((k < 24 || i < HWTOT) && (vals[k] & premask) == pre)
                atomicAdd(&hist[(vals[k] >> shift) & bmask], 1u);
        }
        __syncthreads();

        // Parallel group sums (32 bins per group), then short serial scan.
        int ng = nb >> 5;
        if (tid < ng) {
            unsigned s = 0;
            int base = tid << 5;
            for (int j = 0; j < 32; j++) s += hist[base + j];
            gsum[tid] = s;
        }
        __syncthreads();
        if (tid == 0) {
            unsigned kk = s_k, cum = 0;
            int g = ng - 1;
            for (; g > 0; g--) {
                if (cum + gsum[g] >= kk) break;
                cum += gsum[g];
            }
            int lo = g << 5;
            int bin = lo + 31;
            for (; bin > lo; bin--) {
                if (cum + hist[bin] >= kk) break;
                cum += hist[bin];
            }
            s_prefix = pre | ((unsigned)bin << shift);
            s_k      = kk - cum;
        }
        __syncthreads();
    }

    unsigned thr = s_prefix;
    #pragma unroll
    for (int k = 0; k < NPT; k++) {
        int i = tid + k * 1024;
        if (k < 24 || i < HWTOT)
            fac[i] = (vals[k] >= thr) ? 1 : 0;
    }
}

// ---------------------------------------------------------------------------
// Heavy streaming pass (R7 layout — best measured: ~109us @ 82% DRAM).
// 4 contiguous-strided float4 per thread; block covers one contiguous 16KB
// region (DRAM row locality). Factor loaded first; x read skipped when the
// whole float4 is gated. Streaming stores (write-once output).
// ---------------------------------------------------------------------------
__global__ __launch_bounds__(256) void apply_kernel(const float4* __restrict__ x,
                                                    float4* __restrict__ out) {
    int bl   = blockIdx.y;
    int base = blockIdx.x * 1024 + threadIdx.x;   // block covers 1024 float4s
    const unsigned char* fac = g_factor + bl * HWTOT;

    int      idx[4];
    uchar4   f[4];
    #pragma unroll
    for (int j = 0; j < 4; j++) {
        idx[j] = base + j * 256;                  // < CHW4 exactly (1575*1024)
        int hw4 = idx[j] % HW4;
        f[j] = __ldg(reinterpret_cast<const uchar4*>(fac + hw4 * 4));
    }

    float4 v[4];
    #pragma unroll
    for (int j = 0; j < 4; j++) {
        if ((f[j].x | f[j].y | f[j].z | f[j].w) == 0) {
            v[j] = make_float4(0.f, 0.f, 0.f, 0.f);
        } else {
            v[j] = __ldg(x + (size_t)bl * CHW4 + idx[j]);
            v[j].x *= (float)f[j].x; v[j].y *= (float)f[j].y;
            v[j].z *= (float)f[j].z; v[j].w *= (float)f[j].w;
        }
    }

    #pragma unroll
    for (int j = 0; j < 4; j++)
        __stcs(out + (size_t)bl * CHW4 + idx[j], v[j]);
}

// ---------------------------------------------------------------------------
extern "C" void kernel_launch(void* const* d_in, const int* in_sizes, int n_in,
                              void* d_out, int out_size) {
    const float* x    = (const float*)d_in[0];
    const float* psm  = (const float*)d_in[1];
    const int*   mask = (const int*)d_in[2];

    prep_kernel<<<BL, 1024>>>(psm, mask);

    dim3 grid(CHW4 / 1024, BL);    // 1575 x 20 blocks, 4 float4/thread
    apply_kernel<<<grid, 256>>>((const float4*)x, (float4*)d_out);
}

// round 13
// speedup vs baseline: 1.4749x; 1.0730x over previous
#include <cuda_runtime.h>

#define BB 4
#define LL 5
#define CC 256
#define HH 100
#define WW 252
#define HWTOT (HH*WW)        // 25200
#define BL (BB*LL)           // 20
#define CP 2
#define KSEL 1024
#define HW4 (HWTOT/4)        // 6300
#define CHW4 (CC*HWTOT/4)    // 1,612,800 float4 per (b,l)
#define NPT 25               // values per thread in prep (1024*25 >= 25200)

__device__ unsigned char g_factor[BL*HWTOT];   // ~0.5 MB

// Order-isomorphic transform for signed floats (monotone uint ordering).
__device__ __forceinline__ unsigned f2ord(float f) {
    unsigned u = __float_as_uint(f);
    return u ^ ((u & 0x80000000u) ? 0xFFFFFFFFu : 0x80000000u);
}
__device__ __forceinline__ float ord2f(unsigned u) {
    return __uint_as_float(u ^ ((u & 0x80000000u) ? 0x80000000u : 0xFFFFFFFFu));
}
__device__ __forceinline__ float sigmoidf_(float d) {
    return 1.0f / (1.0f + expf(-d));
}

// ---------------------------------------------------------------------------
// Prep: one block per (b,l).
//  l==0         -> factor = 1 (int4 fill)
//  mask==0, l>0 -> factor = 0 (int4 fill)
//  kept         -> d = max_cp(psm - ego); radix-select exact K-th largest of d
//                  (NO expf in the hot path — sigmoid is monotone, so the
//                  K-th largest sigmoid is sigmoid(d_K); MUFU at 0.5/cyc/SM
//                  made 25600 expf ~28us/block, the real prep bottleneck).
//                  Reference tie class {sigmoid(d) >= sigmoid(d_K)} is a
//                  half-line {d >= d_lo}; d_lo found by a 32-step binary
//                  search over transformed bits (32 expf total).
// ---------------------------------------------------------------------------
__global__ __launch_bounds__(1024) void prep_kernel(const float* __restrict__ psm,
                                                    const int* __restrict__ mask) {
    int bl  = blockIdx.x;
    int l   = bl % LL;
    int b   = bl / LL;
    int tid = threadIdx.x;
    unsigned char* fac = g_factor + bl * HWTOT;

    if (l == 0 || mask[bl] == 0) {
        int fillv = (l == 0) ? 0x01010101 : 0;
        int4 q = make_int4(fillv, fillv, fillv, fillv);
        int4* dst = reinterpret_cast<int4*>(fac);
        for (int i = tid; i < HWTOT / 16; i += 1024) dst[i] = q;   // 25200 = 1575*16
        return;
    }

    const float* p = psm + (size_t)bl * CP * HWTOT;          // psm[b,l,0,:]
    const float* e = psm + (size_t)b * LL * CP * HWTOT;      // psm[b,0,0,:]

    unsigned vals[NPT];
    #pragma unroll
    for (int k = 0; k < NPT; k++) {
        int i = tid + k * 1024;
        unsigned u = 0;                                      // lowest ordinal (inactive)
        if (k < 24 || i < HWTOT) {
            float d0 = __ldg(p + i)         - __ldg(e + i);
            float d1 = __ldg(p + i + HWTOT) - __ldg(e + i + HWTOT);
            u = f2ord(fmaxf(d0, d1));
        }
        vals[k] = u;
    }

    __shared__ unsigned hist[2048];
    __shared__ unsigned gsum[64];
    __shared__ unsigned s_prefix, s_k, s_thr;
    if (tid == 0) { s_prefix = 0u; s_k = KSEL; }

    const int r_shift[3] = {21, 10, 0};
    const int r_bits[3]  = {11, 11, 10};

    for (int r = 0; r < 3; r++) {
        int shift      = r_shift[r];
        int nb         = 1 << r_bits[r];
        unsigned bmask = (unsigned)nb - 1u;

        for (int i = tid; i < nb; i += 1024) hist[i] = 0;
        __syncthreads();

        unsigned pre     = s_prefix;
        unsigned premask = (r == 0) ? 0u : (0xFFFFFFFFu << (shift + r_bits[r]));

        #pragma unroll
        for (int k = 0; k < NPT; k++) {
            int i = tid + k * 1024;
            if ((k < 24 || i < HWTOT) && (vals[k] & premask) == pre)
                atomicAdd(&hist[(vals[k] >> shift) & bmask], 1u);
        }
        __syncthreads();

        int ng = nb >> 5;
        if (tid < ng) {
            unsigned s = 0;
            int base = tid << 5;
            for (int j = 0; j < 32; j++) s += hist[base + j];
            gsum[tid] = s;
        }
        __syncthreads();
        if (tid == 0) {
            unsigned kk = s_k, cum = 0;
            int g = ng - 1;
            for (; g > 0; g--) {
                if (cum + gsum[g] >= kk) break;
                cum += gsum[g];
            }
            int lo = g << 5;
            int bin = lo + 31;
            for (; bin > lo; bin--) {
                if (cum + hist[bin] >= kk) break;
                cum += hist[bin];
            }
            s_prefix = pre | ((unsigned)bin << shift);
            s_k      = kk - cum;
        }
        __syncthreads();
    }

    // Thread 0: threshold in sigmoid space, pulled back to transformed-d space.
    if (tid == 0) {
        unsigned tk  = s_prefix;                 // transformed d_K (exact K-th largest)
        float    sk  = sigmoidf_(ord2f(tk));     // reference threshold value
        unsigned lo = 0, hi = tk;                // min u with sigmoid(ord2f(u)) >= sk
        while (lo < hi) {
            unsigned mid = lo + ((hi - lo) >> 1);
            if (sigmoidf_(ord2f(mid)) >= sk) hi = mid; else lo = mid + 1;
        }
        s_thr = lo;
    }
    __syncthreads();

    unsigned thr = s_thr;
    #pragma unroll
    for (int k = 0; k < NPT; k++) {
        int i = tid + k * 1024;
        if (k < 24 || i < HWTOT)
            fac[i] = (vals[k] >= thr) ? 1 : 0;
    }
}

// ---------------------------------------------------------------------------
// Heavy streaming pass (unchanged — best measured: ~108.4us @ 82.8% DRAM).
// 4 contiguous-strided float4 per thread; block covers one contiguous 16KB
// region (DRAM row locality). Factor loaded first; x read skipped when the
// whole float4 is gated. Streaming stores (write-once output).
// ---------------------------------------------------------------------------
__global__ __launch_bounds__(256) void apply_kernel(const float4* __restrict__ x,
                                                    float4* __restrict__ out) {
    int bl   = blockIdx.y;
    int base = blockIdx.x * 1024 + threadIdx.x;   // block covers 1024 float4s
    const unsigned char* fac = g_factor + bl * HWTOT;

    int      idx[4];
    uchar4   f[4];
    #pragma unroll
    for (int j = 0; j < 4; j++) {
        idx[j] = base + j * 256;                  // < CHW4 exactly (1575*1024)
        int hw4 = idx[j] % HW4;
        f[j] = __ldg(reinterpret_cast<const uchar4*>(fac + hw4 * 4));
    }

    float4 v[4];
    #pragma unroll
    for (int j = 0; j < 4; j++) {
        if ((f[j].x | f[j].y | f[j].z | f[j].w) == 0) {
            v[j] = make_float4(0.f, 0.f, 0.f, 0.f);
        } else {
            v[j] = __ldg(x + (size_t)bl * CHW4 + idx[j]);
            v[j].x *= (float)f[j].x; v[j].y *= (float)f[j].y;
            v[j].z *= (float)f[j].z; v[j].w *= (float)f[j].w;
        }
    }

    #pragma unroll
    for (int j = 0; j < 4; j++)
        __stcs(out + (size_t)bl * CHW4 + idx[j], v[j]);
}

// ---------------------------------------------------------------------------
extern "C" void kernel_launch(void* const* d_in, const int* in_sizes, int n_in,
                              void* d_out, int out_size) {
    const float* x    = (const float*)d_in[0];
    const float* psm  = (const float*)d_in[1];
    const int*   mask = (const int*)d_in[2];

    prep_kernel<<<BL, 1024>>>(psm, mask);

    dim3 grid(CHW4 / 1024, BL);    // 1575 x 20 blocks, 4 float4/thread
    apply_kernel<<<grid, 256>>>((const float4*)x, (float4*)d_out);
}